// round 14
// baseline (speedup 1.0000x reference)
#include <cuda_runtime.h>
#include <cuda_bf16.h>
#include <math.h>

// Problem constants
#define Bn 8192
#define Tn 40
#define En 64
#define NTILES 4992               // ceil(8192*39/64)
#define NCTAS 128

#define FUSED_SMEM (45952*4)      // 183808 B (union of GRU ~167KB and MLP 184KB)

// -------- device scratch (no allocations allowed) --------
__device__ int   g_maskMode;              // 0=u8, 1=int32, 2=float32
__device__ float g_tilepart[NTILES];
__device__ int   g_tasks[NTILES * 64];
__device__ int   g_cnt[Bn];
__device__ int   g_ord[Bn];               // rows sorted by length desc (stable)
__device__ int   g_hist[41];
__device__ int   g_bstart[41];            // sorted-pos start of each length bucket
__device__ int   g_tbase[41];             // task offset base of each bucket
__device__ int   g_flag[NCTAS];
__device__ int   g_ctr;
__device__ int   g_nm;

__device__ __forceinline__ float mval(const void* m, int idx, int mode) {
    if (mode == 1) return ((const int*)m)[idx] ? 1.0f : 0.0f;
    if (mode == 2) return ((const float*)m)[idx];
    return ((const unsigned char*)m)[idx] ? 1.0f : 0.0f;
}
__device__ __forceinline__ float sigf(float v) { return 1.0f / (1.0f + __expf(-v)); }
__device__ __forceinline__ float tanhf_(float v) {
    return 1.0f - 2.0f / (__expf(2.0f * v) + 1.0f);
}

// packed f32x2 helpers
__device__ __forceinline__ unsigned long long dup2(float x) {
    unsigned long long r; unsigned u = __float_as_uint(x);
    asm("mov.b64 %0, {%1, %1};" : "=l"(r) : "r"(u));
    return r;
}
__device__ __forceinline__ void fma2(unsigned long long& d,
                                     unsigned long long a, unsigned long long b) {
    asm("fma.rn.f32x2 %0, %1, %2, %0;" : "+l"(d) : "l"(a), "l"(b));
}
__device__ __forceinline__ float2 unp(unsigned long long v) {
    unsigned lo, hi;
    asm("mov.b64 {%0, %1}, %2;" : "=r"(lo), "=r"(hi) : "l"(v));
    return make_float2(__uint_as_float(lo), __uint_as_float(hi));
}

// tf32 helpers
__device__ __forceinline__ unsigned tf32c(float x) {
    unsigned r; asm("cvt.rna.tf32.f32 %0, %1;" : "=r"(r) : "f"(x)); return r;
}
__device__ __forceinline__ void mma_tf32(float c[4], const uint4& a, const uint2& b) {
    asm("mma.sync.aligned.m16n8k8.row.col.f32.tf32.tf32.f32 "
        "{%0,%1,%2,%3}, {%4,%5,%6,%7}, {%8,%9}, {%0,%1,%2,%3};"
        : "+f"(c[0]), "+f"(c[1]), "+f"(c[2]), "+f"(c[3])
        : "r"(a.x), "r"(a.y), "r"(a.z), "r"(a.w), "r"(b.x), "r"(b.y));
}

// -------- mask dtype probe + hist reset --------
__global__ void detect_k(const int* __restrict__ m32) {
    __shared__ int sB, sF;
    if (threadIdx.x == 0) { sB = 1; sF = 1; }
    if (threadIdx.x < 41) g_hist[threadIdx.x] = 0;
    __syncthreads();
    int okB = 1, okF = 1;
    for (int i = threadIdx.x; i < 2560; i += blockDim.x) {
        int v = m32[i];
        okB = okB && (v == 0 || v == 1);
        okF = okF && (v == 0 || v == 0x3F800000);
    }
    atomicAnd(&sB, okB);
    atomicAnd(&sF, okF);
    __syncthreads();
    if (threadIdx.x == 0) g_maskMode = sB ? 1 : (sF ? 2 : 0);
}

// -------- per-row valid-count + global length histogram + flag/ctr reset --------
__global__ void cnt_k(const void* __restrict__ nmask) {
    const int b = blockIdx.x * 256 + threadIdx.x;
    const int mode = g_maskMode;
    int c = 0;
    #pragma unroll
    for (int tt = 0; tt < 39; ++tt)
        c += (mval(nmask, b * 39 + tt, mode) != 0.0f);
    g_cnt[b] = c;
    int len = c + 1; if (len > 40) len = 40;
    atomicAdd(&g_hist[len], 1);
    if (blockIdx.x == 0) {
        if (threadIdx.x < NCTAS) g_flag[threadIdx.x] = 0;
        if (threadIdx.x == 255) g_ctr = 0;
    }
}

// -------- bucket starts + task bases (closed form) + tail padding --------
__global__ void off2_k() {
    __shared__ int s_total;
    if (threadIdx.x == 0) {
        int run = 0, trun = 0;
        for (int L = 40; L >= 1; --L) {
            g_bstart[L] = run;
            g_tbase[L] = trun;
            run += g_hist[L];
            trun += g_hist[L] * (L - 1);
        }
        g_nm = trun;
        s_total = trun;
    }
    __syncthreads();
    const int total = s_total;
    const int padded = ((total + 63) >> 6) << 6;
    for (int i = total + threadIdx.x; i < padded; i += 64) g_tasks[i] = -1;
}

// -------- parallel stable bucket fill: one warp per length (40 CTAs) --------
__global__ void sortp_k() {
    const int L = 40 - (int)blockIdx.x;   // 40..1
    const int lane = threadIdx.x;
    int pos = g_bstart[L];
    for (int base = 0; base < Bn; base += 32) {
        const int b = base + lane;
        int len = g_cnt[b] + 1; if (len > 40) len = 40;
        const bool p = (len == L);
        const unsigned m = __ballot_sync(0xffffffffu, p);
        if (p) g_ord[pos + __popc(m & ((1u << lane) - 1u))] = b;
        pos += __popc(m);
    }
}

// -------- fill tasks (closed-form offsets), chunk id packed in bits [20..) --------
__global__ void fills_k() {
    const int i = blockIdx.x * 256 + threadIdx.x;   // sorted position
    const int row = g_ord[i];
    const int c = g_cnt[row];
    int len = c + 1; if (len > 40) len = 40;
    const int chunk = i >> 6;
    int off = g_tbase[len] + (i - g_bstart[len]) * c;
    for (int tt = 0; tt < c; ++tt)
        g_tasks[off + tt] = (chunk << 20) | (row << 6) | tt;
}

// -------- MLP smem layout (phase 2) --------
#define O_W1F  0
#define O_W2F  16384
#define O_AFG  24576
#define O_AFX  28672
#define O_AFN  32768
#define O_H1F  36864
#define O_PP   45056
#define O_PN   45312
#define O_B1   45568
#define O_B2   45696
#define O_W3   45760
#define O_RED  45824
#define O_TSK  45888

__device__ __forceinline__ int afidx(int row, int k) {
    const int mt = row >> 4, ks = k >> 3;
    const int lane = ((row & 7) << 2) | (k & 3);
    const int slot = ((row >> 3) & 1) + (((k >> 2) & 1) << 1);
    return (((mt << 3) + ks) << 5 | lane) * 4 + slot;
}
__device__ __forceinline__ int h1idx(int row, int j) {
    const int mt = row >> 4, ks = j >> 3;
    const int lane = ((row & 7) << 2) | (j & 3);
    const int slot = ((row >> 3) & 1) + (((j >> 2) & 1) << 1);
    return (((mt << 4) + ks) << 5 | lane) * 4 + slot;
}

// -------- fused: GRU phase (1024 thr, 1 row/thread) then MLP phase --------
__global__ void __launch_bounds__(1024, 1) fused_k(
    const float* __restrict__ x,
    const float* __restrict__ nub,
    const float* __restrict__ W, const float* __restrict__ U,
    const float* __restrict__ bias,
    const float* __restrict__ w1, const float* __restrict__ b1,
    const float* __restrict__ w2, const float* __restrict__ b2,
    const float* __restrict__ w3, const float* __restrict__ b3,
    float* __restrict__ y)
{
    extern __shared__ float sm[];
    const int tid = threadIdx.x, lane = tid & 31, w = tid >> 5;

    // ================= PHASE 1: GRU on sorted chunk blockIdx.x =================
    {
        float* Ws  = sm;               // 12288  [k][192]
        float* Us  = sm + 12288;       // 12288
        float* Ha  = sm + 24576;       // [k=64][row pitch 66]
        float* Hb  = Ha + 4224;
        float* Xa  = Hb + 4224;
        float* Xb  = Xa + 4224;
        float* zbS = Xb + 4224;        // 64 (bias_z_in + bias_z_rec)
        float* rbS = zbS + 64;
        float* xbS = rbS + 64;
        float* hbS = xbS + 64;

        const int tx = tid & 15, ty = tid >> 4;   // ty 0..63 = row, tx = col quad
        const int c0 = 4 * tx;
        const int ck0 = blockIdx.x * 64;

        for (int i = tid; i < 3072; i += 1024) {
            ((float4*)Ws)[i] = ((const float4*)W)[i];
            ((float4*)Us)[i] = ((const float4*)U)[i];
        }
        for (int i = tid; i < 4224; i += 1024) Ha[i] = 0.0f;
        if (tid < 64) {
            zbS[tid] = bias[tid] + bias[192 + tid];
            rbS[tid] = bias[64 + tid] + bias[256 + tid];
            xbS[tid] = bias[128 + tid];
            hbS[tid] = bias[320 + tid];
        }

        const int row = g_ord[ck0 + ty];
        const int len = g_cnt[row] + 1;
        int ml = g_cnt[g_ord[ck0]] + 1;           // chunk max (sorted desc)
        if (ml > 40) ml = 40;

        // stage X for t=0: one item per thread (row ty, quad tx)
        {
            const float4 v = *(const float4*)&x[(size_t)(row * Tn + 0) * 64 + c0];
            Xa[(c0 + 0) * 66 + ty] = v.x;
            Xa[(c0 + 1) * 66 + ty] = v.y;
            Xa[(c0 + 2) * 66 + ty] = v.z;
            Xa[(c0 + 3) * 66 + ty] = v.w;
        }
        __syncthreads();

        float* Hr = Ha; float* Hw = Hb;
        float* Xc = Xa; float* Xn = Xb;
        float hn[4];
        #pragma unroll
        for (int j = 0; j < 4; ++j) hn[j] = 0.0f;

        for (int t = 0; t < ml; ++t) {
            float4 xp;
            const bool pf = (t + 1 < ml);
            if (pf) xp = *(const float4*)&x[(size_t)(row * Tn + t + 1) * 64 + c0];
            const float m = (t < len) ? 1.0f : 0.0f;

            unsigned long long zac[2], rac[2], xha[2], rha[2];
            zac[0] = *(const unsigned long long*)&zbS[c0];
            zac[1] = *(const unsigned long long*)&zbS[c0 + 2];
            rac[0] = *(const unsigned long long*)&rbS[c0];
            rac[1] = *(const unsigned long long*)&rbS[c0 + 2];
            xha[0] = *(const unsigned long long*)&xbS[c0];
            xha[1] = *(const unsigned long long*)&xbS[c0 + 2];
            rha[0] = *(const unsigned long long*)&hbS[c0];
            rha[1] = *(const unsigned long long*)&hbS[c0 + 2];

            #pragma unroll 8
            for (int k = 0; k < 64; ++k) {
                const float hv = Hr[k * 66 + ty];
                const float xv = Xc[k * 66 + ty];
                const unsigned long long hd = dup2(hv), xd = dup2(xv);
                const ulonglong2 uz = *(const ulonglong2*)&Us[k * 192 + c0];
                const ulonglong2 ur = *(const ulonglong2*)&Us[k * 192 + 64 + c0];
                const ulonglong2 uh = *(const ulonglong2*)&Us[k * 192 + 128 + c0];
                const ulonglong2 wz = *(const ulonglong2*)&Ws[k * 192 + c0];
                const ulonglong2 wr = *(const ulonglong2*)&Ws[k * 192 + 64 + c0];
                const ulonglong2 wh = *(const ulonglong2*)&Ws[k * 192 + 128 + c0];
                fma2(zac[0], hd, uz.x); fma2(zac[1], hd, uz.y);
                fma2(zac[0], xd, wz.x); fma2(zac[1], xd, wz.y);
                fma2(rac[0], hd, ur.x); fma2(rac[1], hd, ur.y);
                fma2(rac[0], xd, wr.x); fma2(rac[1], xd, wr.y);
                fma2(rha[0], hd, uh.x); fma2(rha[1], hd, uh.y);
                fma2(xha[0], xd, wh.x); fma2(xha[1], xd, wh.y);
            }

            #pragma unroll
            for (int q = 0; q < 2; ++q) {
                const float2 zz = unp(zac[q]);
                const float2 rr = unp(rac[q]);
                const float2 xx = unp(xha[q]);
                const float2 hh = unp(rha[q]);
                #pragma unroll
                for (int s = 0; s < 2; ++s) {
                    const int col = c0 + 2 * q + s;
                    const float ho = Hr[col * 66 + ty];
                    const float zval = s ? zz.y : zz.x;
                    const float rval = s ? rr.y : rr.x;
                    const float xval = s ? xx.y : xx.x;
                    const float hval = s ? hh.y : hh.x;
                    const float z  = sigf(zval);
                    const float rg = sigf(rval);
                    const float hc = tanhf_(xval + rg * hval);
                    const float v  = z * ho + (1.0f - z) * hc;
                    const float nv = (m != 0.0f) ? v : ho;
                    hn[2 * q + s] = nv;
                    Hw[col * 66 + ty] = nv;
                }
            }
            { float4 o; o.x = hn[0]; o.y = hn[1]; o.z = hn[2]; o.w = hn[3];
              *(float4*)&y[(size_t)(row * Tn + t) * 64 + c0] = o; }

            if (pf) {
                Xn[(c0 + 0) * 66 + ty] = xp.x;
                Xn[(c0 + 1) * 66 + ty] = xp.y;
                Xn[(c0 + 2) * 66 + ty] = xp.z;
                Xn[(c0 + 3) * 66 + ty] = xp.w;
            }
            __syncthreads();
            { float* tp = Hr; Hr = Hw; Hw = tp; }
            { float* tp = Xc; Xc = Xn; Xn = tp; }
        }

        // carried tail for t >= ml
        for (int t = ml; t < Tn; ++t) {
            float4 o; o.x = hn[0]; o.y = hn[1]; o.z = hn[2]; o.w = hn[3];
            *(float4*)&y[(size_t)(row * Tn + t) * 64 + c0] = o;
        }

        __threadfence();
        __syncthreads();
        if (tid == 0) atomicExch(&g_flag[blockIdx.x], 1);
    }

    // ================= PHASE 2: MLP work-stealing over ready tiles =================
    __syncthreads();
    {
        unsigned* W1F = (unsigned*)(sm + O_W1F);
        unsigned* W2F = (unsigned*)(sm + O_W2F);
        unsigned* AFG = (unsigned*)(sm + O_AFG);
        unsigned* AFX = (unsigned*)(sm + O_AFX);
        unsigned* AFN = (unsigned*)(sm + O_AFN);
        unsigned* H1F = (unsigned*)(sm + O_H1F);
        float* partP = sm + O_PP;
        float* partN = sm + O_PN;
        float* b1s = sm + O_B1;
        float* b2s = sm + O_B2;
        float* w3s = sm + O_W3;
        float* red = sm + O_RED;
        int*   tsk = (int*)(sm + O_TSK);
        volatile int* vflag = (volatile int*)g_flag;

        const int g = lane >> 2, tig = lane & 3;
        const int mt = w & 3, ng = (w >> 2) & 3;
        const bool mmaw = (w < 16);

        for (int idx = tid; idx < 16 * 16 * 32; idx += 1024) {
            const int l = idx & 31, nt = (idx >> 5) & 15, ks = idx >> 9;
            const int gg = l >> 2, tg = l & 3;
            W1F[idx * 2]     = tf32c(w1[(ks * 8 + tg) * 128 + nt * 8 + gg]);
            W1F[idx * 2 + 1] = tf32c(w1[(ks * 8 + tg + 4) * 128 + nt * 8 + gg]);
        }
        for (int idx = tid; idx < 16 * 8 * 32; idx += 1024) {
            const int l = idx & 31, nt = (idx >> 5) & 7, ks = idx >> 8;
            const int gg = l >> 2, tg = l & 3;
            W2F[idx * 2]     = tf32c(w2[(ks * 8 + tg) * 64 + nt * 8 + gg]);
            W2F[idx * 2 + 1] = tf32c(w2[(ks * 8 + tg + 4) * 64 + nt * 8 + gg]);
        }
        if (tid < 128) b1s[tid] = b1[tid];
        if (tid >= 128 && tid < 192) b2s[tid - 128] = b2[tid - 128];
        if (tid >= 192 && tid < 256) w3s[tid - 192] = w3[tid - 192];

        const float b3v = b3[0];
        const float loge = logf(1e-7f);
        const float log1me = logf(1.0f - 1e-7f);
        const int nm = g_nm;
        const int ntiles = (nm + 63) >> 6;
        __shared__ int s_tile;

        for (;;) {
            __syncthreads();   // protect smem reuse + s_tile
            if (tid == 0) {
                const int ti = atomicAdd(&g_ctr, 1);
                int tile = (ti < ntiles) ? (ntiles - 1 - ti) : -1;
                if (tile >= 0) {
                    const int lastp = (tile * 64 + 63 < nm) ? (tile * 64 + 63) : (nm - 1);
                    const int ck = g_tasks[lastp] >> 20;
                    while (vflag[ck] == 0) {}
                }
                s_tile = tile;
            }
            __syncthreads();
            const int tile = s_tile;
            if (tile < 0) break;
            __threadfence();   // acquire for y reads

            if (tid < 64) tsk[tid] = g_tasks[tile * 64 + tid];
            __syncthreads();

            for (int i = tid; i < 1024; i += 1024) {
                const int rowi = i >> 4, kq = i & 15, k0 = kq * 4;
                int tk = tsk[rowi]; if (tk < 0) tk = 0;
                const int b = (tk >> 6) & 0x3FFF;
                const int tt = tk & 63;
                const size_t prow = (size_t)(b * 40 + 1 + tt) * 64 + k0;
                const size_t nrow = (size_t)(b * 39 + tt) * 64 + k0;
                float4 v;
                v = *(const float4*)&y[prow];
                AFG[afidx(rowi, k0)]     = tf32c(v.x);
                AFG[afidx(rowi, k0 + 1)] = tf32c(v.y);
                AFG[afidx(rowi, k0 + 2)] = tf32c(v.z);
                AFG[afidx(rowi, k0 + 3)] = tf32c(v.w);
                v = *(const float4*)&x[prow];
                AFX[afidx(rowi, k0)]     = tf32c(v.x);
                AFX[afidx(rowi, k0 + 1)] = tf32c(v.y);
                AFX[afidx(rowi, k0 + 2)] = tf32c(v.z);
                AFX[afidx(rowi, k0 + 3)] = tf32c(v.w);
                v = *(const float4*)&nub[nrow];
                AFN[afidx(rowi, k0)]     = tf32c(v.x);
                AFN[afidx(rowi, k0 + 1)] = tf32c(v.y);
                AFN[afidx(rowi, k0 + 2)] = tf32c(v.z);
                AFN[afidx(rowi, k0 + 3)] = tf32c(v.w);
            }
            __syncthreads();

            float cg[4][4] = {};
            if (mmaw) {
                #pragma unroll
                for (int ks = 0; ks < 8; ++ks) {
                    const uint4 a = ((const uint4*)AFG)[(mt * 8 + ks) * 32 + lane];
                    #pragma unroll
                    for (int i = 0; i < 4; ++i) {
                        const int nt = ng * 4 + i;
                        const uint2 b = ((const uint2*)W1F)[(ks * 16 + nt) * 32 + lane];
                        mma_tf32(cg[i], a, b);
                    }
                }
            }

            // positive branch
            if (mmaw) {
                float cp[4][4];
                #pragma unroll
                for (int i = 0; i < 4; ++i)
                    #pragma unroll
                    for (int q = 0; q < 4; ++q) cp[i][q] = cg[i][q];
                #pragma unroll
                for (int ks = 0; ks < 8; ++ks) {
                    const uint4 a = ((const uint4*)AFX)[(mt * 8 + ks) * 32 + lane];
                    #pragma unroll
                    for (int i = 0; i < 4; ++i) {
                        const int nt = ng * 4 + i;
                        const uint2 b = ((const uint2*)W1F)[((ks + 8) * 16 + nt) * 32 + lane];
                        mma_tf32(cp[i], a, b);
                    }
                }
                const int row1 = mt * 16 + g;
                #pragma unroll
                for (int i = 0; i < 4; ++i) {
                    const int j0 = (ng * 4 + i) * 8 + 2 * tig;
                    H1F[h1idx(row1, j0)]         = tf32c(fmaxf(cp[i][0] + b1s[j0], 0.0f));
                    H1F[h1idx(row1, j0 + 1)]     = tf32c(fmaxf(cp[i][1] + b1s[j0 + 1], 0.0f));
                    H1F[h1idx(row1 + 8, j0)]     = tf32c(fmaxf(cp[i][2] + b1s[j0], 0.0f));
                    H1F[h1idx(row1 + 8, j0 + 1)] = tf32c(fmaxf(cp[i][3] + b1s[j0 + 1], 0.0f));
                }
            }
            __syncthreads();
            if (mmaw) {
                float c2[2][4] = {};
                #pragma unroll
                for (int ks = 0; ks < 16; ++ks) {
                    const uint4 a = ((const uint4*)H1F)[(mt * 16 + ks) * 32 + lane];
                    #pragma unroll
                    for (int i = 0; i < 2; ++i) {
                        const int nt = ng * 2 + i;
                        const uint2 b = ((const uint2*)W2F)[(ks * 8 + nt) * 32 + lane];
                        mma_tf32(c2[i], a, b);
                    }
                }
                float s1 = 0.0f, s2 = 0.0f;
                #pragma unroll
                for (int i = 0; i < 2; ++i) {
                    const int j0 = (ng * 2 + i) * 8 + 2 * tig;
                    s1 += fmaxf(c2[i][0] + b2s[j0], 0.0f) * w3s[j0]
                        + fmaxf(c2[i][1] + b2s[j0 + 1], 0.0f) * w3s[j0 + 1];
                    s2 += fmaxf(c2[i][2] + b2s[j0], 0.0f) * w3s[j0]
                        + fmaxf(c2[i][3] + b2s[j0 + 1], 0.0f) * w3s[j0 + 1];
                }
                s1 += __shfl_xor_sync(0xffffffffu, s1, 1);
                s1 += __shfl_xor_sync(0xffffffffu, s1, 2);
                s2 += __shfl_xor_sync(0xffffffffu, s2, 1);
                s2 += __shfl_xor_sync(0xffffffffu, s2, 2);
                if (tig == 0) {
                    partP[ng * 64 + mt * 16 + g] = s1;
                    partP[ng * 64 + mt * 16 + 8 + g] = s2;
                }
            }
            __syncthreads();

            // negative branch
            if (mmaw) {
                float cn[4][4];
                #pragma unroll
                for (int i = 0; i < 4; ++i)
                    #pragma unroll
                    for (int q = 0; q < 4; ++q) cn[i][q] = cg[i][q];
                #pragma unroll
                for (int ks = 0; ks < 8; ++ks) {
                    const uint4 a = ((const uint4*)AFN)[(mt * 8 + ks) * 32 + lane];
                    #pragma unroll
                    for (int i = 0; i < 4; ++i) {
                        const int nt = ng * 4 + i;
                        const uint2 b = ((const uint2*)W1F)[((ks + 8) * 16 + nt) * 32 + lane];
                        mma_tf32(cn[i], a, b);
                    }
                }
                const int row1 = mt * 16 + g;
                #pragma unroll
                for (int i = 0; i < 4; ++i) {
                    const int j0 = (ng * 4 + i) * 8 + 2 * tig;
                    H1F[h1idx(row1, j0)]         = tf32c(fmaxf(cn[i][0] + b1s[j0], 0.0f));
                    H1F[h1idx(row1, j0 + 1)]     = tf32c(fmaxf(cn[i][1] + b1s[j0 + 1], 0.0f));
                    H1F[h1idx(row1 + 8, j0)]     = tf32c(fmaxf(cn[i][2] + b1s[j0], 0.0f));
                    H1F[h1idx(row1 + 8, j0 + 1)] = tf32c(fmaxf(cn[i][3] + b1s[j0 + 1], 0.0f));
                }
            }
            __syncthreads();
            if (mmaw) {
                float c2[2][4] = {};
                #pragma unroll
                for (int ks = 0; ks < 16; ++ks) {
                    const uint4 a = ((const uint4*)H1F)[(mt * 16 + ks) * 32 + lane];
                    #pragma unroll
                    for (int i = 0; i < 2; ++i) {
                        const int nt = ng * 2 + i;
                        const uint2 b = ((const uint2*)W2F)[(ks * 8 + nt) * 32 + lane];
                        mma_tf32(c2[i], a, b);
                    }
                }
                float s1 = 0.0f, s2 = 0.0f;
                #pragma unroll
                for (int i = 0; i < 2; ++i) {
                    const int j0 = (ng * 2 + i) * 8 + 2 * tig;
                    s1 += fmaxf(c2[i][0] + b2s[j0], 0.0f) * w3s[j0]
                        + fmaxf(c2[i][1] + b2s[j0 + 1], 0.0f) * w3s[j0 + 1];
                    s2 += fmaxf(c2[i][2] + b2s[j0], 0.0f) * w3s[j0]
                        + fmaxf(c2[i][3] + b2s[j0 + 1], 0.0f) * w3s[j0 + 1];
                }
                s1 += __shfl_xor_sync(0xffffffffu, s1, 1);
                s1 += __shfl_xor_sync(0xffffffffu, s1, 2);
                s2 += __shfl_xor_sync(0xffffffffu, s2, 1);
                s2 += __shfl_xor_sync(0xffffffffu, s2, 2);
                if (tig == 0) {
                    partN[ng * 64 + mt * 16 + g] = s1;
                    partN[ng * 64 + mt * 16 + 8 + g] = s2;
                }
            }
            __syncthreads();

            // per-tile loss partial (deterministic: depends only on tile data)
            if (tid < 64) {
                float term = 0.0f;
                if (tsk[tid] >= 0) {
                    const float lp_ = partP[tid] + partP[64 + tid] + partP[128 + tid]
                                    + partP[192 + tid] + b3v;
                    const float ln_ = partN[tid] + partN[64 + tid] + partN[128 + tid]
                                    + partN[192 + tid] + b3v;
                    const float p  = sigf(lp_);
                    const float pn = sigf(ln_);
                    term = -(p  * log1me + (1.0f - p)  * loge)
                           - (pn * loge  + (1.0f - pn) * log1me);
                }
                red[tid] = term;
            }
            __syncthreads();
            if (tid == 0) {
                float L = 0.0f;
                #pragma unroll
                for (int i = 0; i < 64; ++i) L += red[i];
                g_tilepart[tile] = L;
            }
        }
    }
}

// -------- deterministic final reduction over tile partials --------
__global__ void fin_k(float* __restrict__ out, int out_size) {
    __shared__ float s[256];
    const int nm = g_nm;
    const int ntiles = (nm + 63) >> 6;
    float L = 0.0f;
    for (int i = threadIdx.x; i < ntiles; i += 256) L += g_tilepart[i];
    s[threadIdx.x] = L; __syncthreads();
    for (int off = 128; off; off >>= 1) {
        if (threadIdx.x < off) s[threadIdx.x] += s[threadIdx.x + off];
        __syncthreads();
    }
    if (threadIdx.x == 0) {
        const float cnt = fmaxf((float)nm, 1.0f);
        out[out_size - 1] = s[0] / (2.0f * cnt);
    }
}

extern "C" void kernel_launch(void* const* d_in, const int* in_sizes, int n_in,
                              void* d_out, int out_size) {
    const float* ub    = (const float*)d_in[0];
    const void*  mask  = d_in[1];
    const float* nub   = (const float*)d_in[2];
    const void*  nmask = d_in[3];
    const float* W     = (const float*)d_in[4];
    const float* U     = (const float*)d_in[5];
    const float* bias  = (const float*)d_in[6];
    const float* w1    = (const float*)d_in[7];
    const float* b1    = (const float*)d_in[8];
    const float* w2    = (const float*)d_in[9];
    const float* b2    = (const float*)d_in[10];
    const float* w3    = (const float*)d_in[11];
    const float* b3    = (const float*)d_in[12];
    float* y = (float*)d_out;

    cudaFuncSetAttribute(fused_k, cudaFuncAttributeMaxDynamicSharedMemorySize, FUSED_SMEM);

    detect_k<<<1, 256>>>((const int*)mask);
    cnt_k<<<32, 256>>>(nmask);
    off2_k<<<1, 64>>>();
    sortp_k<<<40, 32>>>();
    fills_k<<<32, 256>>>();
    fused_k<<<NCTAS, 1024, FUSED_SMEM>>>(ub, nub, W, U, bias,
                                         w1, b1, w2, b2, w3, b3, y);
    fin_k<<<1, 256>>>(y, out_size);
}

// round 15
// speedup vs baseline: 2.3649x; 2.3649x over previous
#include <cuda_runtime.h>
#include <cuda_bf16.h>
#include <math.h>

// Problem constants
#define Bn 8192
#define Tn 40
#define En 64
#define NTILES 4992               // ceil(8192*39/64)
#define NCTAS 128
#define NBLK 32                   // row blocks of 256

#define FUSED_SMEM (45952*4)      // 183808 B (union of GRU ~167KB and MLP 184KB)

// -------- device scratch (no allocations allowed) --------
__device__ int   g_maskMode;              // 0=u8, 1=int32, 2=float32
__device__ float g_tilepart[NTILES];
__device__ int   g_tasks[NTILES * 64];
__device__ int   g_cnt[Bn];
__device__ int   g_ord[Bn];               // rows sorted by length desc (stable)
__device__ int   g_bhist[NBLK][41];       // per-block length histogram
__device__ int   g_bbase[NBLK][41];       // per-block base within bucket
__device__ int   g_bstart[41];            // sorted-pos start of each length bucket
__device__ int   g_tbase[41];             // task offset base of each bucket
__device__ int   g_flag[NCTAS];
__device__ int   g_ctr;
__device__ int   g_nm;

__device__ __forceinline__ float mval(const void* m, int idx, int mode) {
    if (mode == 1) return ((const int*)m)[idx] ? 1.0f : 0.0f;
    if (mode == 2) return ((const float*)m)[idx];
    return ((const unsigned char*)m)[idx] ? 1.0f : 0.0f;
}
__device__ __forceinline__ float sigf(float v) { return 1.0f / (1.0f + __expf(-v)); }
__device__ __forceinline__ float tanhf_(float v) {
    return 1.0f - 2.0f / (__expf(2.0f * v) + 1.0f);
}

// packed f32x2 helpers
__device__ __forceinline__ unsigned long long dup2(float x) {
    unsigned long long r; unsigned u = __float_as_uint(x);
    asm("mov.b64 %0, {%1, %1};" : "=l"(r) : "r"(u));
    return r;
}
__device__ __forceinline__ unsigned long long pack2(float a, float b) {
    unsigned long long r;
    asm("mov.b64 %0, {%1, %2};" : "=l"(r)
        : "r"(__float_as_uint(a)), "r"(__float_as_uint(b)));
    return r;
}
__device__ __forceinline__ void fma2(unsigned long long& d,
                                     unsigned long long a, unsigned long long b) {
    asm("fma.rn.f32x2 %0, %1, %2, %0;" : "+l"(d) : "l"(a), "l"(b));
}
__device__ __forceinline__ float2 unp(unsigned long long v) {
    unsigned lo, hi;
    asm("mov.b64 {%0, %1}, %2;" : "=r"(lo), "=r"(hi) : "l"(v));
    return make_float2(__uint_as_float(lo), __uint_as_float(hi));
}

// tf32 helpers
__device__ __forceinline__ unsigned tf32c(float x) {
    unsigned r; asm("cvt.rna.tf32.f32 %0, %1;" : "=r"(r) : "f"(x)); return r;
}
__device__ __forceinline__ void mma_tf32(float c[4], const uint4& a, const uint2& b) {
    asm("mma.sync.aligned.m16n8k8.row.col.f32.tf32.tf32.f32 "
        "{%0,%1,%2,%3}, {%4,%5,%6,%7}, {%8,%9}, {%0,%1,%2,%3};"
        : "+f"(c[0]), "+f"(c[1]), "+f"(c[2]), "+f"(c[3])
        : "r"(a.x), "r"(a.y), "r"(a.z), "r"(a.w), "r"(b.x), "r"(b.y));
}

// -------- mask dtype probe --------
__global__ void detect_k(const int* __restrict__ m32) {
    __shared__ int sB, sF;
    if (threadIdx.x == 0) { sB = 1; sF = 1; }
    __syncthreads();
    int okB = 1, okF = 1;
    for (int i = threadIdx.x; i < 2560; i += blockDim.x) {
        int v = m32[i];
        okB = okB && (v == 0 || v == 1);
        okF = okF && (v == 0 || v == 0x3F800000);
    }
    atomicAnd(&sB, okB);
    atomicAnd(&sF, okF);
    __syncthreads();
    if (threadIdx.x == 0) g_maskMode = sB ? 1 : (sF ? 2 : 0);
}

// -------- per-row valid-count + per-block histogram + flag/ctr reset --------
__global__ void cnt_k(const void* __restrict__ nmask) {
    __shared__ int h[41];
    if (threadIdx.x < 41) h[threadIdx.x] = 0;
    __syncthreads();
    const int b = blockIdx.x * 256 + threadIdx.x;
    const int mode = g_maskMode;
    int c = 0;
    #pragma unroll
    for (int tt = 0; tt < 39; ++tt)
        c += (mval(nmask, b * 39 + tt, mode) != 0.0f);
    g_cnt[b] = c;
    int len = c + 1; if (len > 40) len = 40;
    atomicAdd(&h[len], 1);
    __syncthreads();
    if (threadIdx.x < 41) g_bhist[blockIdx.x][threadIdx.x] = h[threadIdx.x];
    if (blockIdx.x == 0) {
        if (threadIdx.x < NCTAS) g_flag[threadIdx.x] = 0;
        if (threadIdx.x == 255) g_ctr = 0;
    }
}

// -------- bucket starts + task bases + per-block bases (all closed form) --------
__global__ void off3_k() {
    __shared__ int s_total;
    const int tid = threadIdx.x;
    if (tid == 0) {
        int run = 0, trun = 0;
        for (int L = 40; L >= 1; --L) {
            int hl = 0;
            for (int blk = 0; blk < NBLK; ++blk) hl += g_bhist[blk][L];
            g_bstart[L] = run;
            g_tbase[L] = trun;
            run += hl;
            trun += hl * (L - 1);
        }
        g_nm = trun;
        s_total = trun;
    }
    __syncthreads();
    if (tid < 40) {
        const int L = tid + 1;
        int running = 0;
        for (int blk = 0; blk < NBLK; ++blk) {
            g_bbase[blk][L] = running;
            running += g_bhist[blk][L];
        }
    }
    __syncthreads();
    const int total = s_total;
    const int padded = ((total + 63) >> 6) << 6;
    for (int i = total + tid; i < padded; i += 64) g_tasks[i] = -1;
}

// -------- deterministic rank: intra-block prefix count by smem scan --------
__global__ void rank_k() {
    __shared__ unsigned char lens[256];
    const int t = threadIdx.x;
    const int b = blockIdx.x * 256 + t;
    int len = g_cnt[b] + 1; if (len > 40) len = 40;
    lens[t] = (unsigned char)len;
    __syncthreads();
    int intra = 0;
    for (int i = 0; i < 256; ++i) intra += (i < t && lens[i] == (unsigned char)len);
    const int pos = g_bstart[len] + g_bbase[blockIdx.x][len] + intra;
    g_ord[pos] = b;
}

// -------- fill tasks (closed-form offsets), chunk id packed in bits [20..) --------
__global__ void fills_k() {
    const int i = blockIdx.x * 256 + threadIdx.x;   // sorted position
    const int row = g_ord[i];
    const int c = g_cnt[row];
    int len = c + 1; if (len > 40) len = 40;
    const int chunk = i >> 6;
    int off = g_tbase[len] + (i - g_bstart[len]) * c;
    for (int tt = 0; tt < c; ++tt)
        g_tasks[off + tt] = (chunk << 20) | (row << 6) | tt;
}

// -------- MLP smem layout (phase 2) --------
#define O_W1F  0
#define O_W2F  16384
#define O_AFG  24576
#define O_AFX  28672
#define O_AFN  32768
#define O_H1F  36864
#define O_PP   45056
#define O_PN   45312
#define O_B1   45568
#define O_B2   45696
#define O_W3   45760
#define O_RED  45824
#define O_TSK  45888

__device__ __forceinline__ int afidx(int row, int k) {
    const int mt = row >> 4, ks = k >> 3;
    const int lane = ((row & 7) << 2) | (k & 3);
    const int slot = ((row >> 3) & 1) + (((k >> 2) & 1) << 1);
    return (((mt << 3) + ks) << 5 | lane) * 4 + slot;
}
__device__ __forceinline__ int h1idx(int row, int j) {
    const int mt = row >> 4, ks = j >> 3;
    const int lane = ((row & 7) << 2) | (j & 3);
    const int slot = ((row >> 3) & 1) + (((j >> 2) & 1) << 1);
    return (((mt << 4) + ks) << 5 | lane) * 4 + slot;
}

// -------- fused: GRU phase (512 thr, 2 rows/thread) then MLP phase --------
__global__ void __launch_bounds__(512, 1) fused_k(
    const float* __restrict__ x,
    const float* __restrict__ nub,
    const float* __restrict__ W, const float* __restrict__ U,
    const float* __restrict__ bias,
    const float* __restrict__ w1, const float* __restrict__ b1,
    const float* __restrict__ w2, const float* __restrict__ b2,
    const float* __restrict__ w3, const float* __restrict__ b3,
    float* __restrict__ y)
{
    extern __shared__ float sm[];
    const int tid = threadIdx.x, lane = tid & 31, w = tid >> 5;

    // ================= PHASE 1: GRU on sorted chunk blockIdx.x =================
    {
        float* Ws = sm;              // 12288  [k][192]
        float* Us = sm + 12288;      // 12288
        float* Ha = sm + 24576;      // [k=64][row pitch 66]
        float* Hb = Ha + 4224;
        float* Xa = Hb + 4224;
        float* Xb = Xa + 4224;

        const int c0 = 4 * w;
        const int ck0 = blockIdx.x * 64;

        for (int i = tid; i < 3072; i += 512) {
            ((float4*)Ws)[i] = ((const float4*)W)[i];
            ((float4*)Us)[i] = ((const float4*)U)[i];
        }
        for (int i = tid; i < 4224; i += 512) Ha[i] = 0.0f;

        const int r0 = 2 * lane;                 // local rows r0, r0+1
        const int row0 = g_ord[ck0 + r0];
        const int row1 = g_ord[ck0 + r0 + 1];
        const int len0 = g_cnt[row0] + 1;
        const int len1 = g_cnt[row1] + 1;
        int ml = g_cnt[g_ord[ck0]] + 1;          // chunk max (sorted desc)
        if (ml > 40) ml = 40;

        // stage X for t=0: item i -> local row i>>4, quad i&15
        #pragma unroll
        for (int rep = 0; rep < 2; ++rep) {
            const int i = tid + rep * 512;
            const int lr = i >> 4, kq = i & 15;
            const int rr = g_ord[ck0 + lr];
            const float4 v = *(const float4*)&x[(size_t)(rr * Tn + 0) * 64 + 4 * kq];
            Xa[(4 * kq + 0) * 66 + lr] = v.x;
            Xa[(4 * kq + 1) * 66 + lr] = v.y;
            Xa[(4 * kq + 2) * 66 + lr] = v.z;
            Xa[(4 * kq + 3) * 66 + lr] = v.w;
        }

        const unsigned long long bzP0 = pack2(bias[c0] + bias[192 + c0],
                                              bias[c0 + 1] + bias[192 + c0 + 1]);
        const unsigned long long bzP1 = pack2(bias[c0 + 2] + bias[192 + c0 + 2],
                                              bias[c0 + 3] + bias[192 + c0 + 3]);
        const unsigned long long brP0 = pack2(bias[64 + c0] + bias[256 + c0],
                                              bias[64 + c0 + 1] + bias[256 + c0 + 1]);
        const unsigned long long brP1 = pack2(bias[64 + c0 + 2] + bias[256 + c0 + 2],
                                              bias[64 + c0 + 3] + bias[256 + c0 + 3]);
        const unsigned long long bxP0 = pack2(bias[128 + c0], bias[128 + c0 + 1]);
        const unsigned long long bxP1 = pack2(bias[128 + c0 + 2], bias[128 + c0 + 3]);
        const unsigned long long bhP0 = pack2(bias[320 + c0], bias[320 + c0 + 1]);
        const unsigned long long bhP1 = pack2(bias[320 + c0 + 2], bias[320 + c0 + 3]);

        __syncthreads();

        float* Hr = Ha; float* Hw = Hb;
        float* Xc = Xa; float* Xn = Xb;
        float hfin[2][4];
        #pragma unroll
        for (int i = 0; i < 2; ++i)
            #pragma unroll
            for (int j = 0; j < 4; ++j) hfin[i][j] = 0.0f;

        for (int t = 0; t < ml; ++t) {
            float4 xp[2];
            const bool pf = (t + 1 < ml);
            if (pf) {
                #pragma unroll
                for (int rep = 0; rep < 2; ++rep) {
                    const int i = tid + rep * 512;
                    const int lr = i >> 4, kq = i & 15;
                    const int rr = g_ord[ck0 + lr];
                    xp[rep] = *(const float4*)&x[(size_t)(rr * Tn + t + 1) * 64 + 4 * kq];
                }
            }
            const float m0 = (t < len0) ? 1.0f : 0.0f;
            const float m1 = (t < len1) ? 1.0f : 0.0f;

            unsigned long long zac[2][2], rac[2][2], xhac[2][2], rhac[2][2];
            zac[0][0] = bzP0; zac[0][1] = bzP1; zac[1][0] = bzP0; zac[1][1] = bzP1;
            rac[0][0] = brP0; rac[0][1] = brP1; rac[1][0] = brP0; rac[1][1] = brP1;
            xhac[0][0] = bxP0; xhac[0][1] = bxP1; xhac[1][0] = bxP0; xhac[1][1] = bxP1;
            rhac[0][0] = bhP0; rhac[0][1] = bhP1; rhac[1][0] = bhP0; rhac[1][1] = bhP1;

            #pragma unroll 4
            for (int k = 0; k < 64; ++k) {
                const float2 h2 = *(const float2*)&Hr[k * 66 + r0];
                const float2 x2 = *(const float2*)&Xc[k * 66 + r0];
                const ulonglong2 uz = *(const ulonglong2*)&Us[k * 192 + c0];
                const ulonglong2 ur = *(const ulonglong2*)&Us[k * 192 + 64 + c0];
                const ulonglong2 uh = *(const ulonglong2*)&Us[k * 192 + 128 + c0];
                const ulonglong2 wz = *(const ulonglong2*)&Ws[k * 192 + c0];
                const ulonglong2 wr = *(const ulonglong2*)&Ws[k * 192 + 64 + c0];
                const ulonglong2 wh = *(const ulonglong2*)&Ws[k * 192 + 128 + c0];
                const unsigned long long h0 = dup2(h2.x), h1 = dup2(h2.y);
                const unsigned long long x0 = dup2(x2.x), x1 = dup2(x2.y);
                fma2(zac[0][0], h0, uz.x);  fma2(zac[0][1], h0, uz.y);
                fma2(zac[1][0], h1, uz.x);  fma2(zac[1][1], h1, uz.y);
                fma2(zac[0][0], x0, wz.x);  fma2(zac[0][1], x0, wz.y);
                fma2(zac[1][0], x1, wz.x);  fma2(zac[1][1], x1, wz.y);
                fma2(rac[0][0], h0, ur.x);  fma2(rac[0][1], h0, ur.y);
                fma2(rac[1][0], h1, ur.x);  fma2(rac[1][1], h1, ur.y);
                fma2(rac[0][0], x0, wr.x);  fma2(rac[0][1], x0, wr.y);
                fma2(rac[1][0], x1, wr.x);  fma2(rac[1][1], x1, wr.y);
                fma2(rhac[0][0], h0, uh.x); fma2(rhac[0][1], h0, uh.y);
                fma2(rhac[1][0], h1, uh.x); fma2(rhac[1][1], h1, uh.y);
                fma2(xhac[0][0], x0, wh.x); fma2(xhac[0][1], x0, wh.y);
                fma2(xhac[1][0], x1, wh.x); fma2(xhac[1][1], x1, wh.y);
            }

            #pragma unroll
            for (int i = 0; i < 2; ++i) {
                const float m = i ? m1 : m0;
                const int rr = i ? row1 : row0;
                float zv[4], rv[4], xh[4], rh[4];
                { float2 v;
                  v = unp(zac[i][0]);  zv[0] = v.x; zv[1] = v.y;
                  v = unp(zac[i][1]);  zv[2] = v.x; zv[3] = v.y;
                  v = unp(rac[i][0]);  rv[0] = v.x; rv[1] = v.y;
                  v = unp(rac[i][1]);  rv[2] = v.x; rv[3] = v.y;
                  v = unp(xhac[i][0]); xh[0] = v.x; xh[1] = v.y;
                  v = unp(xhac[i][1]); xh[2] = v.x; xh[3] = v.y;
                  v = unp(rhac[i][0]); rh[0] = v.x; rh[1] = v.y;
                  v = unp(rhac[i][1]); rh[2] = v.x; rh[3] = v.y; }
                #pragma unroll
                for (int jj = 0; jj < 4; ++jj) {
                    const float ho = Hr[(c0 + jj) * 66 + r0 + i];
                    const float z = sigf(zv[jj]);
                    const float rg = sigf(rv[jj]);
                    const float hh = tanhf_(xh[jj] + rg * rh[jj]);
                    const float v = z * ho + (1.0f - z) * hh;
                    const float nv = (m != 0.0f) ? v : ho;
                    hfin[i][jj] = nv;
                    Hw[(c0 + jj) * 66 + r0 + i] = nv;
                }
                float4 o; o.x = hfin[i][0]; o.y = hfin[i][1];
                o.z = hfin[i][2]; o.w = hfin[i][3];
                *(float4*)&y[(size_t)(rr * Tn + t) * 64 + c0] = o;
            }

            if (pf) {
                #pragma unroll
                for (int rep = 0; rep < 2; ++rep) {
                    const int i = tid + rep * 512;
                    const int lr = i >> 4, kq = i & 15;
                    Xn[(4 * kq + 0) * 66 + lr] = xp[rep].x;
                    Xn[(4 * kq + 1) * 66 + lr] = xp[rep].y;
                    Xn[(4 * kq + 2) * 66 + lr] = xp[rep].z;
                    Xn[(4 * kq + 3) * 66 + lr] = xp[rep].w;
                }
            }
            __syncthreads();
            { float* tp = Hr; Hr = Hw; Hw = tp; }
            { float* tp = Xc; Xc = Xn; Xn = tp; }
        }

        // carried tail for t >= ml
        for (int t = ml; t < Tn; ++t) {
            #pragma unroll
            for (int i = 0; i < 2; ++i) {
                const int rr = i ? row1 : row0;
                float4 o; o.x = hfin[i][0]; o.y = hfin[i][1];
                o.z = hfin[i][2]; o.w = hfin[i][3];
                *(float4*)&y[(size_t)(rr * Tn + t) * 64 + c0] = o;
            }
        }

        __threadfence();
        __syncthreads();
        if (tid == 0) atomicExch(&g_flag[blockIdx.x], 1);
    }

    // ================= PHASE 2: MLP work-stealing over ready tiles =================
    __syncthreads();
    {
        unsigned* W1F = (unsigned*)(sm + O_W1F);
        unsigned* W2F = (unsigned*)(sm + O_W2F);
        unsigned* AFG = (unsigned*)(sm + O_AFG);
        unsigned* AFX = (unsigned*)(sm + O_AFX);
        unsigned* AFN = (unsigned*)(sm + O_AFN);
        unsigned* H1F = (unsigned*)(sm + O_H1F);
        float* partP = sm + O_PP;
        float* partN = sm + O_PN;
        float* b1s = sm + O_B1;
        float* b2s = sm + O_B2;
        float* w3s = sm + O_W3;
        float* red = sm + O_RED;
        int*   tsk = (int*)(sm + O_TSK);
        volatile int* vflag = (volatile int*)g_flag;

        const int g = lane >> 2, tig = lane & 3;
        const int mt = w & 3, ng = w >> 2;

        for (int idx = tid; idx < 16 * 16 * 32; idx += 512) {
            const int l = idx & 31, nt = (idx >> 5) & 15, ks = idx >> 9;
            const int gg = l >> 2, tg = l & 3;
            W1F[idx * 2]     = tf32c(w1[(ks * 8 + tg) * 128 + nt * 8 + gg]);
            W1F[idx * 2 + 1] = tf32c(w1[(ks * 8 + tg + 4) * 128 + nt * 8 + gg]);
        }
        for (int idx = tid; idx < 16 * 8 * 32; idx += 512) {
            const int l = idx & 31, nt = (idx >> 5) & 7, ks = idx >> 8;
            const int gg = l >> 2, tg = l & 3;
            W2F[idx * 2]     = tf32c(w2[(ks * 8 + tg) * 64 + nt * 8 + gg]);
            W2F[idx * 2 + 1] = tf32c(w2[(ks * 8 + tg + 4) * 64 + nt * 8 + gg]);
        }
        if (tid < 128) b1s[tid] = b1[tid];
        if (tid >= 128 && tid < 192) b2s[tid - 128] = b2[tid - 128];
        if (tid >= 192 && tid < 256) w3s[tid - 192] = w3[tid - 192];

        const float b3v = b3[0];
        const float loge = logf(1e-7f);
        const float log1me = logf(1.0f - 1e-7f);
        const int nm = g_nm;
        const int ntiles = (nm + 63) >> 6;
        __shared__ int s_tile;

        for (;;) {
            __syncthreads();   // protect smem reuse + s_tile
            if (tid == 0) {
                const int ti = atomicAdd(&g_ctr, 1);
                int tile = (ti < ntiles) ? (ntiles - 1 - ti) : -1;
                if (tile >= 0) {
                    const int lastp = (tile * 64 + 63 < nm) ? (tile * 64 + 63) : (nm - 1);
                    const int ck = g_tasks[lastp] >> 20;
                    while (vflag[ck] == 0) {}
                }
                s_tile = tile;
            }
            __syncthreads();
            const int tile = s_tile;
            if (tile < 0) break;
            __threadfence();   // acquire for y reads

            if (tid < 64) tsk[tid] = g_tasks[tile * 64 + tid];
            __syncthreads();

            for (int i = tid; i < 1024; i += 512) {
                const int rowi = i >> 4, kq = i & 15, k0 = kq * 4;
                int tk = tsk[rowi]; if (tk < 0) tk = 0;
                const int b = (tk >> 6) & 0x3FFF;
                const int tt = tk & 63;
                const size_t prow = (size_t)(b * 40 + 1 + tt) * 64 + k0;
                const size_t nrow = (size_t)(b * 39 + tt) * 64 + k0;
                float4 v;
                v = *(const float4*)&y[prow];
                AFG[afidx(rowi, k0)]     = tf32c(v.x);
                AFG[afidx(rowi, k0 + 1)] = tf32c(v.y);
                AFG[afidx(rowi, k0 + 2)] = tf32c(v.z);
                AFG[afidx(rowi, k0 + 3)] = tf32c(v.w);
                v = *(const float4*)&x[prow];
                AFX[afidx(rowi, k0)]     = tf32c(v.x);
                AFX[afidx(rowi, k0 + 1)] = tf32c(v.y);
                AFX[afidx(rowi, k0 + 2)] = tf32c(v.z);
                AFX[afidx(rowi, k0 + 3)] = tf32c(v.w);
                v = *(const float4*)&nub[nrow];
                AFN[afidx(rowi, k0)]     = tf32c(v.x);
                AFN[afidx(rowi, k0 + 1)] = tf32c(v.y);
                AFN[afidx(rowi, k0 + 2)] = tf32c(v.z);
                AFN[afidx(rowi, k0 + 3)] = tf32c(v.w);
            }
            __syncthreads();

            float cg[4][4] = {};
            #pragma unroll
            for (int ks = 0; ks < 8; ++ks) {
                const uint4 a = ((const uint4*)AFG)[(mt * 8 + ks) * 32 + lane];
                #pragma unroll
                for (int i = 0; i < 4; ++i) {
                    const int nt = ng * 4 + i;
                    const uint2 b = ((const uint2*)W1F)[(ks * 16 + nt) * 32 + lane];
                    mma_tf32(cg[i], a, b);
                }
            }

            // positive branch
            {
                float cp[4][4];
                #pragma unroll
                for (int i = 0; i < 4; ++i)
                    #pragma unroll
                    for (int q = 0; q < 4; ++q) cp[i][q] = cg[i][q];
                #pragma unroll
                for (int ks = 0; ks < 8; ++ks) {
                    const uint4 a = ((const uint4*)AFX)[(mt * 8 + ks) * 32 + lane];
                    #pragma unroll
                    for (int i = 0; i < 4; ++i) {
                        const int nt = ng * 4 + i;
                        const uint2 b = ((const uint2*)W1F)[((ks + 8) * 16 + nt) * 32 + lane];
                        mma_tf32(cp[i], a, b);
                    }
                }
                const int row1 = mt * 16 + g;
                #pragma unroll
                for (int i = 0; i < 4; ++i) {
                    const int j0 = (ng * 4 + i) * 8 + 2 * tig;
                    H1F[h1idx(row1, j0)]         = tf32c(fmaxf(cp[i][0] + b1s[j0], 0.0f));
                    H1F[h1idx(row1, j0 + 1)]     = tf32c(fmaxf(cp[i][1] + b1s[j0 + 1], 0.0f));
                    H1F[h1idx(row1 + 8, j0)]     = tf32c(fmaxf(cp[i][2] + b1s[j0], 0.0f));
                    H1F[h1idx(row1 + 8, j0 + 1)] = tf32c(fmaxf(cp[i][3] + b1s[j0 + 1], 0.0f));
                }
            }
            __syncthreads();
            {
                float c2[2][4] = {};
                #pragma unroll
                for (int ks = 0; ks < 16; ++ks) {
                    const uint4 a = ((const uint4*)H1F)[(mt * 16 + ks) * 32 + lane];
                    #pragma unroll
                    for (int i = 0; i < 2; ++i) {
                        const int nt = ng * 2 + i;
                        const uint2 b = ((const uint2*)W2F)[(ks * 8 + nt) * 32 + lane];
                        mma_tf32(c2[i], a, b);
                    }
                }
                float s1 = 0.0f, s2 = 0.0f;
                #pragma unroll
                for (int i = 0; i < 2; ++i) {
                    const int j0 = (ng * 2 + i) * 8 + 2 * tig;
                    s1 += fmaxf(c2[i][0] + b2s[j0], 0.0f) * w3s[j0]
                        + fmaxf(c2[i][1] + b2s[j0 + 1], 0.0f) * w3s[j0 + 1];
                    s2 += fmaxf(c2[i][2] + b2s[j0], 0.0f) * w3s[j0]
                        + fmaxf(c2[i][3] + b2s[j0 + 1], 0.0f) * w3s[j0 + 1];
                }
                s1 += __shfl_xor_sync(0xffffffffu, s1, 1);
                s1 += __shfl_xor_sync(0xffffffffu, s1, 2);
                s2 += __shfl_xor_sync(0xffffffffu, s2, 1);
                s2 += __shfl_xor_sync(0xffffffffu, s2, 2);
                if (tig == 0) {
                    partP[ng * 64 + mt * 16 + g] = s1;
                    partP[ng * 64 + mt * 16 + 8 + g] = s2;
                }
            }
            __syncthreads();

            // negative branch
            {
                float cn[4][4];
                #pragma unroll
                for (int i = 0; i < 4; ++i)
                    #pragma unroll
                    for (int q = 0; q < 4; ++q) cn[i][q] = cg[i][q];
                #pragma unroll
                for (int ks = 0; ks < 8; ++ks) {
                    const uint4 a = ((const uint4*)AFN)[(mt * 8 + ks) * 32 + lane];
                    #pragma unroll
                    for (int i = 0; i < 4; ++i) {
                        const int nt = ng * 4 + i;
                        const uint2 b = ((const uint2*)W1F)[((ks + 8) * 16 + nt) * 32 + lane];
                        mma_tf32(cn[i], a, b);
                    }
                }
                const int row1 = mt * 16 + g;
                #pragma unroll
                for (int i = 0; i < 4; ++i) {
                    const int j0 = (ng * 4 + i) * 8 + 2 * tig;
                    H1F[h1idx(row1, j0)]         = tf32c(fmaxf(cn[i][0] + b1s[j0], 0.0f));
                    H1F[h1idx(row1, j0 + 1)]     = tf32c(fmaxf(cn[i][1] + b1s[j0 + 1], 0.0f));
                    H1F[h1idx(row1 + 8, j0)]     = tf32c(fmaxf(cn[i][2] + b1s[j0], 0.0f));
                    H1F[h1idx(row1 + 8, j0 + 1)] = tf32c(fmaxf(cn[i][3] + b1s[j0 + 1], 0.0f));
                }
            }
            __syncthreads();
            {
                float c2[2][4] = {};
                #pragma unroll
                for (int ks = 0; ks < 16; ++ks) {
                    const uint4 a = ((const uint4*)H1F)[(mt * 16 + ks) * 32 + lane];
                    #pragma unroll
                    for (int i = 0; i < 2; ++i) {
                        const int nt = ng * 2 + i;
                        const uint2 b = ((const uint2*)W2F)[(ks * 8 + nt) * 32 + lane];
                        mma_tf32(c2[i], a, b);
                    }
                }
                float s1 = 0.0f, s2 = 0.0f;
                #pragma unroll
                for (int i = 0; i < 2; ++i) {
                    const int j0 = (ng * 2 + i) * 8 + 2 * tig;
                    s1 += fmaxf(c2[i][0] + b2s[j0], 0.0f) * w3s[j0]
                        + fmaxf(c2[i][1] + b2s[j0 + 1], 0.0f) * w3s[j0 + 1];
                    s2 += fmaxf(c2[i][2] + b2s[j0], 0.0f) * w3s[j0]
                        + fmaxf(c2[i][3] + b2s[j0 + 1], 0.0f) * w3s[j0 + 1];
                }
                s1 += __shfl_xor_sync(0xffffffffu, s1, 1);
                s1 += __shfl_xor_sync(0xffffffffu, s1, 2);
                s2 += __shfl_xor_sync(0xffffffffu, s2, 1);
                s2 += __shfl_xor_sync(0xffffffffu, s2, 2);
                if (tig == 0) {
                    partN[ng * 64 + mt * 16 + g] = s1;
                    partN[ng * 64 + mt * 16 + 8 + g] = s2;
                }
            }
            __syncthreads();

            // per-tile loss partial (deterministic: depends only on tile data)
            if (tid < 64) {
                float term = 0.0f;
                if (tsk[tid] >= 0) {
                    const float lp_ = partP[tid] + partP[64 + tid] + partP[128 + tid]
                                    + partP[192 + tid] + b3v;
                    const float ln_ = partN[tid] + partN[64 + tid] + partN[128 + tid]
                                    + partN[192 + tid] + b3v;
                    const float p  = sigf(lp_);
                    const float pn = sigf(ln_);
                    term = -(p  * log1me + (1.0f - p)  * loge)
                           - (pn * loge  + (1.0f - pn) * log1me);
                }
                red[tid] = term;
            }
            __syncthreads();
            if (tid == 0) {
                float L = 0.0f;
                #pragma unroll
                for (int i = 0; i < 64; ++i) L += red[i];
                g_tilepart[tile] = L;
            }
        }
    }
}

// -------- deterministic final reduction over tile partials --------
__global__ void fin_k(float* __restrict__ out, int out_size) {
    __shared__ float s[256];
    const int nm = g_nm;
    const int ntiles = (nm + 63) >> 6;
    float L = 0.0f;
    for (int i = threadIdx.x; i < ntiles; i += 256) L += g_tilepart[i];
    s[threadIdx.x] = L; __syncthreads();
    for (int off = 128; off; off >>= 1) {
        if (threadIdx.x < off) s[threadIdx.x] += s[threadIdx.x + off];
        __syncthreads();
    }
    if (threadIdx.x == 0) {
        const float cnt = fmaxf((float)nm, 1.0f);
        out[out_size - 1] = s[0] / (2.0f * cnt);
    }
}

extern "C" void kernel_launch(void* const* d_in, const int* in_sizes, int n_in,
                              void* d_out, int out_size) {
    const float* ub    = (const float*)d_in[0];
    const void*  mask  = d_in[1];
    const float* nub   = (const float*)d_in[2];
    const void*  nmask = d_in[3];
    const float* W     = (const float*)d_in[4];
    const float* U     = (const float*)d_in[5];
    const float* bias  = (const float*)d_in[6];
    const float* w1    = (const float*)d_in[7];
    const float* b1    = (const float*)d_in[8];
    const float* w2    = (const float*)d_in[9];
    const float* b2    = (const float*)d_in[10];
    const float* w3    = (const float*)d_in[11];
    const float* b3    = (const float*)d_in[12];
    float* y = (float*)d_out;

    cudaFuncSetAttribute(fused_k, cudaFuncAttributeMaxDynamicSharedMemorySize, FUSED_SMEM);

    detect_k<<<1, 256>>>((const int*)mask);
    cnt_k<<<32, 256>>>(nmask);
    off3_k<<<1, 64>>>();
    rank_k<<<32, 256>>>();
    fills_k<<<32, 256>>>();
    fused_k<<<NCTAS, 512, FUSED_SMEM>>>(ub, nub, W, U, bias,
                                        w1, b1, w2, b2, w3, b3, y);
    fin_k<<<1, 256>>>(y, out_size);
}